// round 1
// baseline (speedup 1.0000x reference)
#include <cuda_runtime.h>
#include <stdint.h>

#define NN 100000
#define CC 128
#define EE 1600000
#define EPSV 1e-5f
#define MIS_ITERS 32

// ---------------- scratch (device globals; no allocation) ----------------
__device__ float g_agg[NN * CC];      // SpMM accumulator; reused as pooled
__device__ float g_h0[NN * CC];
__device__ float g_h1[NN * CC];
__device__ float g_posagg[NN * 3];
__device__ unsigned long long g_key[NN];
__device__ unsigned long long g_nmax[NN];   // reused as bestkey in cluster stage
__device__ unsigned char g_active[NN];
__device__ unsigned char g_sel[NN];
__device__ unsigned char g_nb[NN];
__device__ unsigned char g_mis[NN];
__device__ int g_cl[NN];
__device__ int g_cluster[NN];
__device__ double g_sum[CC];
__device__ double g_sumsq[CC];
__device__ float g_scale[CC];
__device__ float g_shift[CC];
__device__ int g_nactive;

// ---------------- zero / init kernels ----------------
__global__ void k_zero_layer() {  // zeros agg + BN stats
    int t = blockIdx.x * blockDim.x + threadIdx.x;
    if (t < NN * CC / 4) ((float4*)g_agg)[t] = make_float4(0.f, 0.f, 0.f, 0.f);
    if (t < CC) { g_sum[t] = 0.0; g_sumsq[t] = 0.0; }
}

__global__ void k_zero_pos() {
    int t = blockIdx.x * blockDim.x + threadIdx.x;
    if (t < NN * 3) g_posagg[t] = 0.f;
}

__global__ void k_zero_pool() {
    int t = blockIdx.x * blockDim.x + threadIdx.x;
    if (t < NN * CC / 4) ((float4*)g_agg)[t] = make_float4(0.f, 0.f, 0.f, 0.f);
}

__global__ void k_mis_init() {
    int t = blockIdx.x * blockDim.x + threadIdx.x;
    if (t < NN) {
        g_active[t] = 1; g_mis[t] = 0; g_sel[t] = 0; g_nb[t] = 0;
        g_nmax[t] = 0ULL; g_cl[t] = -1;
    }
    if (t == 0) g_nactive = NN;
}

__global__ void k_zero_best() {
    int t = blockIdx.x * blockDim.x + threadIdx.x;
    if (t < NN) g_nmax[t] = 0ULL;
}

// ---------------- SpMM: agg[dst] += e_w * x[src]  (warp per edge) ----------------
__global__ void __launch_bounds__(256) k_spmm(const float* __restrict__ xin,
                                              const int* __restrict__ src,
                                              const int* __restrict__ dst,
                                              const float* __restrict__ ew) {
    const float* x = xin ? xin : g_h0;
    int gt = blockIdx.x * 256 + threadIdx.x;
    int w = gt >> 5, lane = gt & 31;
    if (w >= EE) return;
    int s = __ldg(src + w), d = __ldg(dst + w);
    float wt = __ldg(ew + w);
    float4 v = *(const float4*)(x + (size_t)s * CC + lane * 4);
    float* a = g_agg + (size_t)d * CC + lane * 4;
    atomicAdd(a + 0, wt * v.x);
    atomicAdd(a + 1, wt * v.y);
    atomicAdd(a + 2, wt * v.z);
    atomicAdd(a + 3, wt * v.w);
}

// posagg[dst] += e_w * (pos[src] - pos[dst])   (thread per edge)
__global__ void k_posagg(const float* __restrict__ pos, const int* __restrict__ src,
                         const int* __restrict__ dst, const float* __restrict__ ew) {
    int e = blockIdx.x * blockDim.x + threadIdx.x;
    if (e >= EE) return;
    int s = src[e], d = dst[e];
    float w = ew[e];
    atomicAdd(&g_posagg[d * 3 + 0], w * (pos[s * 3 + 0] - pos[d * 3 + 0]));
    atomicAdd(&g_posagg[d * 3 + 1], w * (pos[s * 3 + 1] - pos[d * 3 + 1]));
    atomicAdd(&g_posagg[d * 3 + 2], w * (pos[s * 3 + 2] - pos[d * 3 + 2]));
}

// ---------------- fused GEMM: out = X@Wr + agg@Wm + posagg@Wp + b ----------------
// Stacked-K GEMM [N,256]x[256,128]: BM=64, BN=64, BK=16, 128 thr, TM=8, TN=4
__global__ void __launch_bounds__(128) k_gemm(const float* __restrict__ Xin,
                                              const float* __restrict__ Wr,
                                              const float* __restrict__ Wm,
                                              const float* __restrict__ Wp,
                                              const float* __restrict__ bias,
                                              int outsel) {
    __shared__ float As[16][64];
    __shared__ float Bs[16][64];
    const float* X = Xin ? Xin : g_h0;
    float* out = outsel ? g_h1 : g_h0;
    int bm = blockIdx.x * 64;
    int bn = blockIdx.y * 64;
    int tid = threadIdx.x;
    int tx = tid & 15, ty = tid >> 4;
    float acc[8][4];
#pragma unroll
    for (int i = 0; i < 8; i++)
#pragma unroll
        for (int j = 0; j < 4; j++) acc[i][j] = 0.f;

    for (int kt = 0; kt < 256; kt += 16) {
#pragma unroll
        for (int v = 0; v < 2; v++) {
            int idx = tid * 8 + v * 4;
            // A tile load (transposed store)
            int m = idx >> 4, kk = idx & 15;
            int row = bm + m;
            int k = kt + kk;
            const float* SA = (k < 128) ? X : g_agg;
            float4 val = make_float4(0.f, 0.f, 0.f, 0.f);
            if (row < NN) val = *(const float4*)(SA + (size_t)row * CC + (k & 127));
            As[kk + 0][m] = val.x; As[kk + 1][m] = val.y;
            As[kk + 2][m] = val.z; As[kk + 3][m] = val.w;
            // B tile load
            int kb = idx >> 6;
            int cb = idx & 63;
            int k2 = kt + kb;
            const float* SB = (k2 < 128) ? Wr : Wm;
            *(float4*)&Bs[kb][cb] = *(const float4*)(SB + (size_t)(k2 & 127) * CC + bn + cb);
        }
        __syncthreads();
#pragma unroll
        for (int k = 0; k < 16; k++) {
            float a[8], b[4];
            *(float4*)&a[0] = *(const float4*)&As[k][ty * 8];
            *(float4*)&a[4] = *(const float4*)&As[k][ty * 8 + 4];
            *(float4*)&b[0] = *(const float4*)&Bs[k][tx * 4];
#pragma unroll
            for (int i = 0; i < 8; i++)
#pragma unroll
                for (int j = 0; j < 4; j++) acc[i][j] += a[i] * b[j];
        }
        __syncthreads();
    }
#pragma unroll
    for (int i = 0; i < 8; i++) {
        int row = bm + ty * 8 + i;
        if (row >= NN) break;
        float p0 = g_posagg[row * 3 + 0], p1 = g_posagg[row * 3 + 1], p2 = g_posagg[row * 3 + 2];
#pragma unroll
        for (int j = 0; j < 4; j++) {
            int col = bn + tx * 4 + j;
            float r = acc[i][j] + bias[col]
                    + p0 * Wp[0 * CC + col] + p1 * Wp[1 * CC + col] + p2 * Wp[2 * CC + col];
            out[(size_t)row * CC + col] = r;
        }
    }
}

// ---------------- BatchNorm ----------------
#define BN_ROWS 125
__global__ void __launch_bounds__(128) k_bnstats(int l) {
    const float* h = l ? g_h1 : g_h0;
    int c = threadIdx.x;
    int r0 = blockIdx.x * BN_ROWS;
    int r1 = min(r0 + BN_ROWS, NN);
    double s = 0.0, s2 = 0.0;
    for (int r = r0; r < r1; r++) {
        float v = h[(size_t)r * CC + c];
        s += v; s2 += (double)v * v;
    }
    atomicAdd(&g_sum[c], s);
    atomicAdd(&g_sumsq[c], s2);
}

__global__ void k_bnfin(const float* __restrict__ g, const float* __restrict__ be) {
    int c = threadIdx.x;
    float mu = (float)(g_sum[c] / NN);
    float var = (float)(g_sumsq[c] / NN) - mu * mu;
    float sc = g[c] * rsqrtf(var + EPSV);
    g_scale[c] = sc;
    g_shift[c] = be[c] - mu * sc;
}

__global__ void k_bnrelu(int l) {
    float* h = l ? g_h1 : g_h0;
    int t = blockIdx.x * blockDim.x + threadIdx.x;
    if (t >= NN * CC / 4) return;
    int c = (t * 4) & (CC - 1);
    float4 v = ((float4*)h)[t];
    v.x = fmaxf(fmaf(v.x, g_scale[c + 0], g_shift[c + 0]), 0.f);
    v.y = fmaxf(fmaf(v.y, g_scale[c + 1], g_shift[c + 1]), 0.f);
    v.z = fmaxf(fmaf(v.z, g_scale[c + 2], g_shift[c + 2]), 0.f);
    v.w = fmaxf(fmaf(v.w, g_scale[c + 3], g_shift[c + 3]), 0.f);
    ((float4*)h)[t] = v;
}

// ---------------- score -> order-isomorphic key (replaces argsort) ----------------
__global__ void __launch_bounds__(256) k_key(const float* __restrict__ ws) {
    int gt = blockIdx.x * 256 + threadIdx.x;
    int node = gt >> 5, lane = gt & 31;
    if (node >= NN) return;
    float4 a = *(const float4*)(g_h1 + (size_t)node * CC + lane * 4);
    float4 b = *(const float4*)(ws + lane * 4);
    float p = a.x * b.x + a.y * b.y + a.z * b.z + a.w * b.w;
#pragma unroll
    for (int o = 16; o; o >>= 1) p += __shfl_xor_sync(0xFFFFFFFFu, p, o);
    if (lane == 0) {
        unsigned u = __float_as_uint(p);
        u = (u & 0x80000000u) ? ~u : (u | 0x80000000u);
        g_key[node] = ((unsigned long long)u << 32) | (unsigned)(NN - 1 - node);
    }
}

// ---------------- MIS iteration kernels (symmetrized graph, both dirs per edge) ----
__global__ void k_mis_nmax(const int* __restrict__ src, const int* __restrict__ dst) {
    if (g_nactive == 0) return;
    int stride = gridDim.x * blockDim.x;
    for (int e = blockIdx.x * blockDim.x + threadIdx.x; e < EE; e += stride) {
        int s = src[e], d = dst[e];
        if (g_active[s]) atomicMax(&g_nmax[d], g_key[s]);
        if (g_active[d]) atomicMax(&g_nmax[s], g_key[d]);
    }
}

__global__ void k_mis_sel() {
    if (g_nactive == 0) return;
    int stride = gridDim.x * blockDim.x;
    for (int i = blockIdx.x * blockDim.x + threadIdx.x; i < NN; i += stride) {
        unsigned char a = g_active[i];
        unsigned char sl = (a && (g_key[i] > g_nmax[i])) ? 1 : 0;
        g_sel[i] = sl;
        if (sl) g_mis[i] = 1;
    }
}

__global__ void k_mis_nb(const int* __restrict__ src, const int* __restrict__ dst) {
    if (g_nactive == 0) return;
    int stride = gridDim.x * blockDim.x;
    for (int e = blockIdx.x * blockDim.x + threadIdx.x; e < EE; e += stride) {
        int s = src[e], d = dst[e];
        if (g_sel[s]) g_nb[d] = 1;
        if (g_sel[d]) g_nb[s] = 1;
    }
}

__global__ void k_mis_upd() {
    int stride = gridDim.x * blockDim.x;
    for (int i = blockIdx.x * blockDim.x + threadIdx.x; i < NN; i += stride) {
        if (g_active[i] && (g_sel[i] || g_nb[i])) {
            g_active[i] = 0;
            atomicSub(&g_nactive, 1);
        }
        g_nmax[i] = 0ULL;  // fresh for next iteration
        g_nb[i] = 0;
    }
}

// ---------------- cluster assignment ----------------
__global__ void k_best(const int* __restrict__ src, const int* __restrict__ dst) {
    int stride = gridDim.x * blockDim.x;
    for (int e = blockIdx.x * blockDim.x + threadIdx.x; e < EE; e += stride) {
        int s = src[e], d = dst[e];
        if (g_mis[s]) atomicMax(&g_nmax[d], g_key[s]);
        if (g_mis[d]) atomicMax(&g_nmax[s], g_key[d]);
    }
}

__global__ void k_cl(const int* __restrict__ src, const int* __restrict__ dst) {
    int stride = gridDim.x * blockDim.x;
    for (int e = blockIdx.x * blockDim.x + threadIdx.x; e < EE; e += stride) {
        int s = src[e], d = dst[e];
        if (g_mis[s] && g_key[s] == g_nmax[d]) atomicMax(&g_cl[d], s);
        if (g_mis[d] && g_key[d] == g_nmax[s]) atomicMax(&g_cl[s], d);
    }
}

__global__ void k_cluster() {
    int i = blockIdx.x * blockDim.x + threadIdx.x;
    if (i >= NN) return;
    g_cluster[i] = g_mis[i] ? i : (g_cl[i] >= 0 ? g_cl[i] : i);
}

// pooled = segment_max(h1, cluster); h1 >= 0 so int-bits atomicMax with 0-init
__global__ void __launch_bounds__(256) k_pool() {
    int gt = blockIdx.x * 256 + threadIdx.x;
    int node = gt >> 5, lane = gt & 31;
    if (node >= NN) return;
    int cl = g_cluster[node];
    float4 v = *(const float4*)(g_h1 + (size_t)node * CC + lane * 4);
    int* p = (int*)(g_agg + (size_t)cl * CC + lane * 4);
    atomicMax(p + 0, __float_as_int(v.x));
    atomicMax(p + 1, __float_as_int(v.y));
    atomicMax(p + 2, __float_as_int(v.z));
    atomicMax(p + 3, __float_as_int(v.w));
}

// ---------------- outputs ----------------
__global__ void k_out_x(float* __restrict__ out, int out_size) {
    int t = blockIdx.x * blockDim.x + threadIdx.x;
    if (t >= NN * CC / 4) return;
    if (4 * t + 3 >= out_size) return;
    int node = t >> 5;  // CC/4 = 32 float4s per row
    float4 v = g_mis[node] ? ((float4*)g_agg)[t] : make_float4(0.f, 0.f, 0.f, 0.f);
    ((float4*)out)[t] = v;
}

__global__ void k_out_tail(float* __restrict__ out, const int* __restrict__ src,
                           const int* __restrict__ dst, const float* __restrict__ ew,
                           const float* __restrict__ pos, int out_size) {
    const int O1 = NN * CC;
    const int TAIL = 3 * EE + 5 * NN;
    int stride = gridDim.x * blockDim.x;
    for (int t = blockIdx.x * blockDim.x + threadIdx.x; t < TAIL; t += stride) {
        int o = O1 + t;
        if (o >= out_size) return;
        float val;
        if (t < EE) {
            val = (float)g_cluster[src[t]];
        } else if (t < 2 * EE) {
            val = (float)g_cluster[dst[t - EE]];
        } else if (t < 3 * EE) {
            val = ew[t - 2 * EE];
        } else if (t < 3 * EE + 3 * NN) {
            int j = t - 3 * EE;
            val = g_mis[j / 3] ? pos[j] : 0.f;
        } else if (t < 3 * EE + 4 * NN) {
            val = 0.f;  // batch
        } else {
            val = g_mis[t - (3 * EE + 4 * NN)] ? 1.f : 0.f;
        }
        out[o] = val;
    }
}

// ---------------- launch ----------------
extern "C" void kernel_launch(void* const* d_in, const int* in_sizes, int n_in,
                              void* d_out, int out_size) {
    const float* x   = (const float*)d_in[0];
    const int*   ei  = (const int*)d_in[1];
    const float* ew  = (const float*)d_in[2];
    const float* pos = (const float*)d_in[3];
    const float* Wr0 = (const float*)d_in[5];
    const float* Wm0 = (const float*)d_in[6];
    const float* Wp0 = (const float*)d_in[7];
    const float* b0  = (const float*)d_in[8];
    const float* g0  = (const float*)d_in[9];
    const float* be0 = (const float*)d_in[10];
    const float* Wr1 = (const float*)d_in[11];
    const float* Wm1 = (const float*)d_in[12];
    const float* Wp1 = (const float*)d_in[13];
    const float* b1  = (const float*)d_in[14];
    const float* g1  = (const float*)d_in[15];
    const float* be1 = (const float*)d_in[16];
    const float* wsc = (const float*)d_in[17];
    float* out = (float*)d_out;

    const int E = in_sizes[1] / 2;
    const int* src = ei;
    const int* dst = ei + E;
    (void)E;

    const int NB4   = (NN * CC / 4 + 255) / 256;  // 12500
    const int EWARP = (EE * 32 + 255) / 256;      // 200000 (warp/edge)
    const int EB    = (EE + 255) / 256;           // 6250
    const int EBS   = 1563;                       // grid-stride edge kernels
    const int NBS   = 98;                         // grid-stride node kernels
    const int NWARP = (NN * 32 + 255) / 256;      // 12500 (warp/node)
    const int NBn   = (NN + 255) / 256;           // 391
    dim3 ggrid((NN + 63) / 64, 2);

    // ---- layer 0 ----
    k_zero_layer<<<NB4, 256>>>();
    k_zero_pos<<<(NN * 3 + 255) / 256, 256>>>();
    k_spmm<<<EWARP, 256>>>(x, src, dst, ew);
    k_posagg<<<EB, 256>>>(pos, src, dst, ew);
    k_gemm<<<ggrid, 128>>>(x, Wr0, Wm0, Wp0, b0, 0);
    k_bnstats<<<(NN + BN_ROWS - 1) / BN_ROWS, 128>>>(0);
    k_bnfin<<<1, 128>>>(g0, be0);
    k_bnrelu<<<NB4, 256>>>(0);

    // ---- layer 1 (posagg reused) ----
    k_zero_layer<<<NB4, 256>>>();
    k_spmm<<<EWARP, 256>>>(nullptr, src, dst, ew);
    k_gemm<<<ggrid, 128>>>(nullptr, Wr1, Wm1, Wp1, b1, 1);
    k_bnstats<<<(NN + BN_ROWS - 1) / BN_ROWS, 128>>>(1);
    k_bnfin<<<1, 128>>>(g1, be1);
    k_bnrelu<<<NB4, 256>>>(1);

    // ---- KMIS ----
    k_key<<<NWARP, 256>>>(wsc);
    k_mis_init<<<NBn, 256>>>();
    for (int it = 0; it < MIS_ITERS; it++) {
        k_mis_nmax<<<EBS, 256>>>(src, dst);
        k_mis_sel<<<NBS, 256>>>();
        k_mis_nb<<<EBS, 256>>>(src, dst);
        k_mis_upd<<<NBS, 256>>>();
    }
    k_zero_best<<<NBn, 256>>>();
    k_best<<<EBS, 256>>>(src, dst);
    k_cl<<<EBS, 256>>>(src, dst);
    k_cluster<<<NBn, 256>>>();

    // ---- pooling + outputs ----
    k_zero_pool<<<NB4, 256>>>();
    k_pool<<<NWARP, 256>>>();
    k_out_x<<<NB4, 256>>>(out, out_size);
    k_out_tail<<<8192, 256>>>(out, src, dst, ew, pos, out_size);
}

// round 2
// speedup vs baseline: 1.5245x; 1.5245x over previous
#include <cuda_runtime.h>
#include <stdint.h>

#define NN 100000
#define CC 128
#define EE 1600000
#define EPSV 1e-5f
#define MIS_ITERS 32

// ---------------- scratch (device globals; no allocation) ----------------
__device__ float g_agg[NN * CC];      // SpMM accumulator; reused as pooled
__device__ float g_h0[NN * CC];
__device__ float g_h1[NN * CC];
__device__ float g_posagg[NN * 3];
__device__ unsigned long long g_key[NN];    // immutable rank key
__device__ unsigned long long g_akey[NN];   // key while active, 0 when inactive
__device__ unsigned long long g_nmax[NN];   // per-iter neighbor max; reused as best in cluster stage
__device__ unsigned char g_nb[NN];
__device__ unsigned char g_mis[NN];
__device__ int g_cluster[NN];
__device__ int2 g_elA[EE];
__device__ int2 g_elB[EE];
__device__ int g_ecnt[2];                   // [0]->elA count, [1]->elB count
__device__ int g_nactive;
__device__ double g_sum[CC];
__device__ double g_sumsq[CC];
__device__ float g_scale[CC];
__device__ float g_shift[CC];

// ---------------- zero kernels ----------------
__global__ void k_zero_layer(int withpos) {  // zeros agg (+posagg) + BN stats
    int t = blockIdx.x * blockDim.x + threadIdx.x;
    if (t < NN * CC / 4) ((float4*)g_agg)[t] = make_float4(0.f, 0.f, 0.f, 0.f);
    if (withpos && t < NN * 3 / 4) ((float4*)g_posagg)[t] = make_float4(0.f, 0.f, 0.f, 0.f);
    if (t < CC) { g_sum[t] = 0.0; g_sumsq[t] = 0.0; }
}

// ---------------- SpMM: agg[dst] += e_w * x[src]  (warp per edge, v4 red) --------
__global__ void __launch_bounds__(256) k_spmm(const float* __restrict__ xin,
                                              const int* __restrict__ src,
                                              const int* __restrict__ dst,
                                              const float* __restrict__ ew) {
    const float* x = xin ? xin : g_h0;
    int gt = blockIdx.x * 256 + threadIdx.x;
    int w = gt >> 5, lane = gt & 31;
    if (w >= EE) return;
    int s = __ldg(src + w), d = __ldg(dst + w);
    float wt = __ldg(ew + w);
    float4 v = *(const float4*)(x + (size_t)s * CC + lane * 4);
    float* a = g_agg + (size_t)d * CC + lane * 4;
    asm volatile("red.global.add.v4.f32 [%0], {%1, %2, %3, %4};"
                 :: "l"(a), "f"(wt * v.x), "f"(wt * v.y), "f"(wt * v.z), "f"(wt * v.w)
                 : "memory");
}

// posagg[dst] += e_w * (pos[src] - pos[dst])   (thread per edge)
__global__ void k_posagg(const float* __restrict__ pos, const int* __restrict__ src,
                         const int* __restrict__ dst, const float* __restrict__ ew) {
    int e = blockIdx.x * blockDim.x + threadIdx.x;
    if (e >= EE) return;
    int s = src[e], d = dst[e];
    float w = ew[e];
    atomicAdd(&g_posagg[d * 3 + 0], w * (pos[s * 3 + 0] - pos[d * 3 + 0]));
    atomicAdd(&g_posagg[d * 3 + 1], w * (pos[s * 3 + 1] - pos[d * 3 + 1]));
    atomicAdd(&g_posagg[d * 3 + 2], w * (pos[s * 3 + 2] - pos[d * 3 + 2]));
}

// ---------------- fused GEMM + BN stats ----------------
// out = [X | agg] @ [Wr ; Wm] + posagg@Wp + b ; also accumulates col sum/sumsq
// BM=128, BN=128(full), BK=16, 256 threads, TM=8, TN=8
__global__ void __launch_bounds__(256, 2) k_gemm(const float* __restrict__ Xin,
                                                 const float* __restrict__ Wr,
                                                 const float* __restrict__ Wm,
                                                 const float* __restrict__ Wp,
                                                 const float* __restrict__ bias,
                                                 int outsel) {
    __shared__ float As[16][128];
    __shared__ float Bs[16][128];
    __shared__ float cs[128], cq[128];
    const float* X = Xin ? Xin : g_h0;
    float* out = outsel ? g_h1 : g_h0;
    int bm = blockIdx.x * 128;
    int tid = threadIdx.x;
    if (tid < 128) { cs[tid] = 0.f; cq[tid] = 0.f; }
    int tx = tid & 15, ty = tid >> 4;
    float acc[8][8];
#pragma unroll
    for (int i = 0; i < 8; i++)
#pragma unroll
        for (int j = 0; j < 8; j++) acc[i][j] = 0.f;

    for (int kt = 0; kt < 256; kt += 16) {
#pragma unroll
        for (int v = 0; v < 2; v++) {  // A tile (transposed store)
            int f = tid + v * 256;
            int m = f >> 2, kq = f & 3;
            int row = bm + m, k = kt + kq * 4;
            const float* SA = (k < 128) ? X : g_agg;
            float4 val = make_float4(0.f, 0.f, 0.f, 0.f);
            if (row < NN) val = *(const float4*)(SA + (size_t)row * CC + (k & 127));
            As[kq * 4 + 0][m] = val.x; As[kq * 4 + 1][m] = val.y;
            As[kq * 4 + 2][m] = val.z; As[kq * 4 + 3][m] = val.w;
        }
#pragma unroll
        for (int v = 0; v < 2; v++) {  // B tile
            int f = tid + v * 256;
            int kb = f >> 5, cb = (f & 31) * 4;
            int k2 = kt + kb;
            const float* SB = (k2 < 128) ? Wr : Wm;
            *(float4*)&Bs[kb][cb] = *(const float4*)(SB + (size_t)(k2 & 127) * CC + cb);
        }
        __syncthreads();
#pragma unroll
        for (int k = 0; k < 16; k++) {
            float a[8], b[8];
            *(float4*)&a[0] = *(const float4*)&As[k][ty * 8];
            *(float4*)&a[4] = *(const float4*)&As[k][ty * 8 + 4];
            *(float4*)&b[0] = *(const float4*)&Bs[k][tx * 8];
            *(float4*)&b[4] = *(const float4*)&Bs[k][tx * 8 + 4];
#pragma unroll
            for (int i = 0; i < 8; i++)
#pragma unroll
                for (int j = 0; j < 8; j++) acc[i][j] += a[i] * b[j];
        }
        __syncthreads();
    }
    // epilogue: bias + pos term, write, accumulate BN stats
    float bb[8], wp0[8], wp1[8], wp2[8];
#pragma unroll
    for (int j = 0; j < 8; j++) {
        int col = tx * 8 + j;
        bb[j] = bias[col]; wp0[j] = Wp[col]; wp1[j] = Wp[CC + col]; wp2[j] = Wp[2 * CC + col];
    }
    float s_[8], q_[8];
#pragma unroll
    for (int j = 0; j < 8; j++) { s_[j] = 0.f; q_[j] = 0.f; }
#pragma unroll
    for (int i = 0; i < 8; i++) {
        int row = bm + ty * 8 + i;
        if (row < NN) {
            float p0 = g_posagg[row * 3 + 0], p1 = g_posagg[row * 3 + 1], p2 = g_posagg[row * 3 + 2];
            float r[8];
#pragma unroll
            for (int j = 0; j < 8; j++) {
                float t = acc[i][j] + bb[j] + p0 * wp0[j] + p1 * wp1[j] + p2 * wp2[j];
                r[j] = t; s_[j] += t; q_[j] += t * t;
            }
            *(float4*)(out + (size_t)row * CC + tx * 8) = make_float4(r[0], r[1], r[2], r[3]);
            *(float4*)(out + (size_t)row * CC + tx * 8 + 4) = make_float4(r[4], r[5], r[6], r[7]);
        }
    }
#pragma unroll
    for (int j = 0; j < 8; j++) {
        atomicAdd(&cs[tx * 8 + j], s_[j]);
        atomicAdd(&cq[tx * 8 + j], q_[j]);
    }
    __syncthreads();
    if (tid < 128) {
        atomicAdd(&g_sum[tid], (double)cs[tid]);
        atomicAdd(&g_sumsq[tid], (double)cq[tid]);
    }
}

// ---------------- BatchNorm finalize / apply ----------------
__global__ void k_bnfin(const float* __restrict__ g, const float* __restrict__ be) {
    int c = threadIdx.x;
    float mu = (float)(g_sum[c] / NN);
    float var = (float)(g_sumsq[c] / NN) - mu * mu;
    float sc = g[c] * rsqrtf(var + EPSV);
    g_scale[c] = sc;
    g_shift[c] = be[c] - mu * sc;
}

__global__ void k_bnrelu() {  // layer 0 only
    int t = blockIdx.x * blockDim.x + threadIdx.x;
    if (t >= NN * CC / 4) return;
    int c = (t * 4) & (CC - 1);
    float4 v = ((float4*)g_h0)[t];
    v.x = fmaxf(fmaf(v.x, g_scale[c + 0], g_shift[c + 0]), 0.f);
    v.y = fmaxf(fmaf(v.y, g_scale[c + 1], g_shift[c + 1]), 0.f);
    v.z = fmaxf(fmaf(v.z, g_scale[c + 2], g_shift[c + 2]), 0.f);
    v.w = fmaxf(fmaf(v.w, g_scale[c + 3], g_shift[c + 3]), 0.f);
    ((float4*)g_h0)[t] = v;
}

// layer 1: BN+ReLU + score key + MIS node-state init (warp per node)
__global__ void __launch_bounds__(256) k_bnrelu_key(const float* __restrict__ ws) {
    int gt = blockIdx.x * 256 + threadIdx.x;
    int node = gt >> 5, lane = gt & 31;
    if (node >= NN) return;
    int c = lane * 4;
    float4 v = *(float4*)(g_h1 + (size_t)node * CC + c);
    v.x = fmaxf(fmaf(v.x, g_scale[c + 0], g_shift[c + 0]), 0.f);
    v.y = fmaxf(fmaf(v.y, g_scale[c + 1], g_shift[c + 1]), 0.f);
    v.z = fmaxf(fmaf(v.z, g_scale[c + 2], g_shift[c + 2]), 0.f);
    v.w = fmaxf(fmaf(v.w, g_scale[c + 3], g_shift[c + 3]), 0.f);
    *(float4*)(g_h1 + (size_t)node * CC + c) = v;
    float4 w = *(const float4*)(ws + c);
    float p = v.x * w.x + v.y * w.y + v.z * w.z + v.w * w.w;
#pragma unroll
    for (int o = 16; o; o >>= 1) p += __shfl_xor_sync(0xFFFFFFFFu, p, o);
    if (lane == 0) {
        unsigned u = __float_as_uint(p);
        u = (u & 0x80000000u) ? ~u : (u | 0x80000000u);
        unsigned long long key = ((unsigned long long)u << 32) | (unsigned)(NN - 1 - node);
        g_key[node] = key;
        g_akey[node] = key;
        g_nmax[node] = 0ULL;
        g_mis[node] = 0;
        g_nb[node] = 0;
        if (node == 0) g_nactive = NN;
    }
}

// ---------------- MIS with edge-list compaction ----------------
__global__ void k_einit(const int* __restrict__ src, const int* __restrict__ dst) {
    int e = blockIdx.x * blockDim.x + threadIdx.x;
    if (e < EE) g_elA[e] = make_int2(src[e], dst[e]);
    if (e == 0) { g_ecnt[0] = EE; g_ecnt[1] = 0; }
}

// pass1: compute neighbor-max keys AND compact surviving edges (both endpoints active)
__global__ void k_mis_pass1(int inb) {
    if (g_nactive == 0) return;
    int cnt = g_ecnt[inb];
    const int2* in = inb ? g_elB : g_elA;
    int2* outl = inb ? g_elA : g_elB;
    int* outc = &g_ecnt[1 - inb];
    int stride = gridDim.x * blockDim.x;
    for (int e = blockIdx.x * blockDim.x + threadIdx.x; e < cnt; e += stride) {
        int2 p = in[e];
        unsigned long long ks = g_akey[p.x];
        unsigned long long kd = g_akey[p.y];
        if (ks && kd) {
            int o = atomicAdd(outc, 1);
            outl[o] = p;
            atomicMax(&g_nmax[p.y], ks);
            atomicMax(&g_nmax[p.x], kd);
        }
    }
}

// pass2: neighbor-of-selected marking (sel derived on the fly)
__global__ void k_mis_pass2(int inb) {
    if (g_nactive == 0) return;
    int outb = 1 - inb;
    int cnt = g_ecnt[outb];
    const int2* el = outb ? g_elB : g_elA;
    int stride = gridDim.x * blockDim.x;
    for (int e = blockIdx.x * blockDim.x + threadIdx.x; e < cnt; e += stride) {
        int2 p = el[e];
        if (g_akey[p.x] > g_nmax[p.x]) g_nb[p.y] = 1;
        if (g_akey[p.y] > g_nmax[p.y]) g_nb[p.x] = 1;
    }
}

// upd: finalize selection, deactivate, clear per-iter state, reset stale counter
__global__ void k_mis_upd(int inb) {
    if (g_nactive == 0) return;
    if (blockIdx.x == 0 && threadIdx.x == 0) g_ecnt[inb] = 0;  // next iteration's out-buffer
    int i = blockIdx.x * blockDim.x + threadIdx.x;
    if (i >= NN) return;
    unsigned long long a = g_akey[i];
    if (a) {
        if (a > g_nmax[i]) {            // selected -> MIS
            g_mis[i] = 1;
            g_akey[i] = 0;
            atomicSub(&g_nactive, 1);
        } else if (g_nb[i]) {           // neighbor of selected -> removed
            g_akey[i] = 0;
            atomicSub(&g_nactive, 1);
        }
    }
    g_nmax[i] = 0ULL;
    g_nb[i] = 0;
}

// ---------------- cluster: best MIS neighbor by key (id decoded from key) --------
__global__ void k_best(const int* __restrict__ src, const int* __restrict__ dst) {
    int e = blockIdx.x * blockDim.x + threadIdx.x;
    if (e >= EE) return;
    int s = src[e], d = dst[e];
    if (g_mis[s]) atomicMax(&g_nmax[d], g_key[s]);
    if (g_mis[d]) atomicMax(&g_nmax[s], g_key[d]);
}

__global__ void k_zero_pool() {
    int t = blockIdx.x * blockDim.x + threadIdx.x;
    if (t < NN * CC / 4) ((float4*)g_agg)[t] = make_float4(0.f, 0.f, 0.f, 0.f);
}

// pool (+cluster decode): h1>=0 post-ReLU so int-bits atomicMax with 0-init
__global__ void __launch_bounds__(256) k_pool() {
    int gt = blockIdx.x * 256 + threadIdx.x;
    int node = gt >> 5, lane = gt & 31;
    if (node >= NN) return;
    int cl;
    if (g_mis[node]) cl = node;
    else {
        unsigned long long b = g_nmax[node];
        cl = b ? (NN - 1 - (int)(unsigned)(b & 0xFFFFFFFFULL)) : node;
    }
    if (lane == 0) g_cluster[node] = cl;
    float4 v = *(const float4*)(g_h1 + (size_t)node * CC + lane * 4);
    int* p = (int*)(g_agg + (size_t)cl * CC + lane * 4);
    atomicMax(p + 0, __float_as_int(v.x));
    atomicMax(p + 1, __float_as_int(v.y));
    atomicMax(p + 2, __float_as_int(v.z));
    atomicMax(p + 3, __float_as_int(v.w));
}

// ---------------- outputs ----------------
__global__ void k_out_x(float* __restrict__ out, int out_size) {
    int t = blockIdx.x * blockDim.x + threadIdx.x;
    if (t >= NN * CC / 4) return;
    if (4 * t + 3 >= out_size) return;
    int node = t >> 5;
    float4 v = g_mis[node] ? ((float4*)g_agg)[t] : make_float4(0.f, 0.f, 0.f, 0.f);
    ((float4*)out)[t] = v;
}

__global__ void k_out_tail(float* __restrict__ out, const int* __restrict__ src,
                           const int* __restrict__ dst, const float* __restrict__ ew,
                           const float* __restrict__ pos, int out_size) {
    const int O1 = NN * CC;
    const int TAIL = 3 * EE + 5 * NN;
    int stride = gridDim.x * blockDim.x;
    for (int t = blockIdx.x * blockDim.x + threadIdx.x; t < TAIL; t += stride) {
        int o = O1 + t;
        if (o >= out_size) return;
        float val;
        if (t < EE) {
            val = (float)g_cluster[src[t]];
        } else if (t < 2 * EE) {
            val = (float)g_cluster[dst[t - EE]];
        } else if (t < 3 * EE) {
            val = ew[t - 2 * EE];
        } else if (t < 3 * EE + 3 * NN) {
            int j = t - 3 * EE;
            val = g_mis[j / 3] ? pos[j] : 0.f;
        } else if (t < 3 * EE + 4 * NN) {
            val = 0.f;  // batch
        } else {
            val = g_mis[t - (3 * EE + 4 * NN)] ? 1.f : 0.f;
        }
        out[o] = val;
    }
}

// ---------------- launch ----------------
extern "C" void kernel_launch(void* const* d_in, const int* in_sizes, int n_in,
                              void* d_out, int out_size) {
    const float* x   = (const float*)d_in[0];
    const int*   ei  = (const int*)d_in[1];
    const float* ew  = (const float*)d_in[2];
    const float* pos = (const float*)d_in[3];
    const float* Wr0 = (const float*)d_in[5];
    const float* Wm0 = (const float*)d_in[6];
    const float* Wp0 = (const float*)d_in[7];
    const float* b0  = (const float*)d_in[8];
    const float* g0  = (const float*)d_in[9];
    const float* be0 = (const float*)d_in[10];
    const float* Wr1 = (const float*)d_in[11];
    const float* Wm1 = (const float*)d_in[12];
    const float* Wp1 = (const float*)d_in[13];
    const float* b1  = (const float*)d_in[14];
    const float* g1  = (const float*)d_in[15];
    const float* be1 = (const float*)d_in[16];
    const float* wsc = (const float*)d_in[17];
    float* out = (float*)d_out;

    const int E = in_sizes[1] / 2;
    const int* src = ei;
    const int* dst = ei + E;
    (void)E;

    const int NB4   = (NN * CC / 4 + 255) / 256;  // 12500
    const int EWARP = (EE * 32 + 255) / 256;      // 200000
    const int EB    = (EE + 255) / 256;           // 6250
    const int NWARP = (NN * 32 + 255) / 256;      // 12500
    const int NBn   = (NN + 255) / 256;           // 391
    const int GGRID = (NN + 127) / 128;           // 782

    // ---- layer 0 ----
    k_zero_layer<<<NB4, 256>>>(1);
    k_spmm<<<EWARP, 256>>>(x, src, dst, ew);
    k_posagg<<<EB, 256>>>(pos, src, dst, ew);
    k_gemm<<<GGRID, 256>>>(x, Wr0, Wm0, Wp0, b0, 0);
    k_bnfin<<<1, 128>>>(g0, be0);
    k_bnrelu<<<NB4, 256>>>();

    // ---- layer 1 (posagg reused) ----
    k_zero_layer<<<NB4, 256>>>(0);
    k_spmm<<<EWARP, 256>>>(nullptr, src, dst, ew);
    k_gemm<<<GGRID, 256>>>(nullptr, Wr1, Wm1, Wp1, b1, 1);
    k_bnfin<<<1, 128>>>(g1, be1);
    k_bnrelu_key<<<NWARP, 256>>>(wsc);

    // ---- KMIS with compaction ----
    k_einit<<<EB, 256>>>(src, dst);
    for (int it = 0; it < MIS_ITERS; it++) {
        int inb = it & 1;
        k_mis_pass1<<<1024, 256>>>(inb);
        k_mis_pass2<<<1024, 256>>>(inb);
        k_mis_upd<<<NBn, 256>>>(inb);
    }
    k_best<<<EB, 256>>>(src, dst);

    // ---- pooling + outputs ----
    k_zero_pool<<<NB4, 256>>>();
    k_pool<<<NWARP, 256>>>();
    k_out_x<<<NB4, 256>>>(out, out_size);
    k_out_tail<<<2048, 256>>>(out, src, dst, ew, pos, out_size);
}